// round 15
// baseline (speedup 1.0000x reference)
#include <cuda_runtime.h>
#include <cuda_bf16.h>
#include <cstdint>

#define NN 100000
#define EE 1600000
#define DD 128
#define NEXP 8
#define EPSV 1e-5f
#define NBLK 592
#define GT (NBLK * 256)
#define AGG_NBLK 296

// ================= scratch (static device globals) =================
__device__ int   g_deg[NN];
__device__ int   g_off[NN];
__device__ int   g_cur[NN];
__device__ float g_inv_deg[NN];
__device__ int   g_srcs[EE];
__device__ int   g_bsum2[NBLK];
__device__ int   g_barrier[8];
__device__ int   g_is64;
__device__ float g_agg0[NN * DD];
__device__ float g_stats_s[NEXP * DD];
__device__ float g_stats_q[NEXP * DD];
__device__ float g_scale[NEXP * DD];
__device__ float g_shift[NEXP * DD];
__device__ char  g_wt_hi[16][65536];     // per (e,l): 2 chunks x [128n][128k] bf16, swizzled
__device__ char  g_wt_lo[16][65536];
__device__ float g_h_all[(size_t)NEXP * NN * DD];     // [8][N][128] pre-BN layer-0 h
__device__ float g_agg1_all[(size_t)NEXP * NN * DD];  // [8][N][128]
__device__ float g_out_tmp[(size_t)NEXP * NN * DD];   // [8][N][128] layer-1 outputs

// ================= host-side streams/events (pre-main init; host objects only) ========
struct SideStream {
    cudaStream_t s2;
    cudaEvent_t evFork, evPrep, evG;
    cudaEvent_t evA[NEXP];
    SideStream() {
        cudaStreamCreateWithFlags(&s2, cudaStreamNonBlocking);
        cudaEventCreateWithFlags(&evFork, cudaEventDisableTiming);
        cudaEventCreateWithFlags(&evPrep, cudaEventDisableTiming);
        cudaEventCreateWithFlags(&evG, cudaEventDisableTiming);
        for (int i = 0; i < NEXP; i++)
            cudaEventCreateWithFlags(&evA[i], cudaEventDisableTiming);
    }
};
static SideStream g_ss;

// ================= device helpers =================
__device__ __forceinline__ uint32_t smem_u32(const void* p) {
    uint32_t a;
    asm("{ .reg .u64 t; cvta.to.shared.u64 t, %1; cvt.u32.u64 %0, t; }" : "=r"(a) : "l"(p));
    return a;
}
__device__ __forceinline__ void ldsm4(uint32_t* r, uint32_t addr) {
    asm volatile("ldmatrix.sync.aligned.m8n8.x4.shared.b16 {%0,%1,%2,%3}, [%4];"
        : "=r"(r[0]), "=r"(r[1]), "=r"(r[2]), "=r"(r[3]) : "r"(addr));
}
__device__ __forceinline__ void mma16816(float* d, const uint32_t* a, const uint32_t* b) {
    asm volatile("mma.sync.aligned.m16n8k16.row.col.f32.bf16.bf16.f32 "
        "{%0,%1,%2,%3}, {%4,%5,%6,%7}, {%8,%9}, {%0,%1,%2,%3};"
        : "+f"(d[0]), "+f"(d[1]), "+f"(d[2]), "+f"(d[3])
        : "r"(a[0]), "r"(a[1]), "r"(a[2]), "r"(a[3]), "r"(b[0]), "r"(b[1]));
}
__device__ __forceinline__ int swz(int row, int kbyte) {
    return row * 256 + ((((kbyte >> 4) ^ (row & 7)) << 4) | (kbyte & 15));
}
__device__ __forceinline__ void cp16(uint32_t dst, const void* src) {
    asm volatile("cp.async.cg.shared.global [%0], [%1], 16;" :: "r"(dst), "l"(src));
}
#define CP_COMMIT() asm volatile("cp.async.commit_group;" ::: "memory")
#define CP_WAIT1() asm volatile("cp.async.wait_group 1;" ::: "memory")
#define CP_WAIT0() asm volatile("cp.async.wait_group 0;" ::: "memory")

// ================= software grid barrier =================
__device__ __forceinline__ void grid_bar(int slot) {
    __syncthreads();
    if (threadIdx.x == 0) {
        __threadfence();
        int arrived = atomicAdd(&g_barrier[slot], 1) + 1;
        if (arrived < NBLK) {
            while (((volatile int*)g_barrier)[slot] < NBLK) { }
        }
        __threadfence();
    }
    __syncthreads();
}

// ================= init =================
__global__ void k_init(const int* __restrict__ ei32) {
    int t = threadIdx.x;
    if (t < 8) g_barrier[t] = 0;
    for (int i = t; i < NEXP * DD; i += 1024) { g_stats_s[i] = 0.f; g_stats_q[i] = 0.f; }
    if (t == 0) {
        int hz = 1;
        for (int i = 0; i < 64; i++)
            if (ei32[2 * i + 1] != 0) { hz = 0; break; }
        g_is64 = hz;
    }
}

// ================= fused CSR build + layer-0 aggregation =================
__global__ void __launch_bounds__(256)
k_csr_agg0(const int* __restrict__ ei32, const float* __restrict__ x,
           float* __restrict__ agg0)
{
    int tid = threadIdx.x, b = blockIdx.x;
    int gt = b * 256 + tid;
    __shared__ int s[256];
    __shared__ int bs[NBLK];

    for (int i = gt; i < NN; i += GT) g_deg[i] = 0;
    grid_bar(0);

    int is64 = g_is64;
    for (int i = gt; i < EE; i += GT) {
        int d = is64 ? ei32[2 * (EE + i)] : ei32[EE + i];
        if ((unsigned)d < NN) atomicAdd(&g_deg[d], 1);
    }
    grid_bar(1);

    int base0 = gt * 2;
    int d0 = (base0     < NN) ? g_deg[base0]     : 0;
    int d1 = (base0 + 1 < NN) ? g_deg[base0 + 1] : 0;
    int tsum = d0 + d1;
    s[tid] = tsum;
    __syncthreads();
    for (int o = 1; o < 256; o <<= 1) {
        int a = (tid >= o) ? s[tid - o] : 0;
        __syncthreads();
        s[tid] += a;
        __syncthreads();
    }
    if (tid == 255) g_bsum2[b] = s[255];
    grid_bar(2);

    if (b == 0) {
        for (int i = tid; i < NBLK; i += 256) bs[i] = g_bsum2[i];
        __syncthreads();
        if (tid == 0) {
            int run = 0;
            for (int i = 0; i < NBLK; i++) { int v = bs[i]; bs[i] = run; run += v; }
        }
        __syncthreads();
        for (int i = tid; i < NBLK; i += 256) g_bsum2[i] = bs[i];
    }
    grid_bar(3);

    {
        int tbase = g_bsum2[b] + (s[tid] - tsum);
        if (base0 < NN) {
            g_off[base0] = tbase;
            g_cur[base0] = tbase;
            g_inv_deg[base0] = 1.0f / (float)(d0 > 0 ? d0 : 1);
        }
        if (base0 + 1 < NN) {
            int o1 = tbase + d0;
            g_off[base0 + 1] = o1;
            g_cur[base0 + 1] = o1;
            g_inv_deg[base0 + 1] = 1.0f / (float)(d1 > 0 ? d1 : 1);
        }
    }
    grid_bar(4);

    for (int i = gt; i < EE; i += GT) {
        int d  = is64 ? ei32[2 * (EE + i)] : ei32[EE + i];
        int sv = is64 ? ei32[2 * i]        : ei32[i];
        if ((unsigned)d < NN && (unsigned)sv < NN) {
            int pos = atomicAdd(&g_cur[d], 1);
            g_srcs[pos] = sv;
        }
    }
    grid_bar(5);

    {
        int gw = gt >> 5, lane = tid & 31;
        const int NW = NBLK * 8;
        const float4* f4 = (const float4*)x;
        for (int node = gw; node < NN; node += NW) {
            int start = g_off[node];
            int cnt   = g_cur[node] - start;
            float4 acc = make_float4(0.f, 0.f, 0.f, 0.f);
            int j = 0;
#define GB(U) \
            { \
                int si[U]; \
                _Pragma("unroll") for (int u = 0; u < U; u++) si[u] = g_srcs[start + j + u]; \
                float4 v[U]; \
                _Pragma("unroll") for (int u = 0; u < U; u++) v[u] = f4[si[u] * 32 + lane]; \
                _Pragma("unroll") for (int u = 0; u < U; u++) { \
                    acc.x += v[u].x; acc.y += v[u].y; acc.z += v[u].z; acc.w += v[u].w; \
                } \
                j += U; \
            }
            for (; j + 8 <= cnt;) GB(8)
            if (j + 4 <= cnt) GB(4)
            if (j + 2 <= cnt) GB(2)
            if (j + 1 <= cnt) GB(1)
#undef GB
            float scv = g_inv_deg[node];
            ((float4*)agg0)[node * 32 + lane] =
                make_float4(acc.x * scv, acc.y * scv, acc.z * scv, acc.w * scv);
        }
    }
}

// ================= per-expert layer-1 aggregation (PERSISTENT, BN+ReLU on gather) =====
// 296 CTAs x 256 thr: occupies only ~25% of SM thread slots so concurrent
// gemm1 CTAs (other stream) can co-schedule instead of being starved.
__global__ void __launch_bounds__(256)
k_agg(const float* __restrict__ feat, float* __restrict__ out,
      const float* __restrict__ scale, const float* __restrict__ shift)
{
    int gw0 = (blockIdx.x * 256 + threadIdx.x) >> 5;
    int lane = threadIdx.x & 31;
    const int NW = AGG_NBLK * 8;
    const float4* f4 = (const float4*)feat;
    float4 sc4 = ((const float4*)scale)[lane];
    float4 sh4 = ((const float4*)shift)[lane];

    for (int gw = gw0; gw < NN; gw += NW) {
        int start = g_off[gw];
        int cnt   = g_cur[gw] - start;
        float4 acc = make_float4(0.f, 0.f, 0.f, 0.f);
        int j = 0;
#define GB(U) \
        { \
            int si[U]; \
            _Pragma("unroll") for (int u = 0; u < U; u++) si[u] = g_srcs[start + j + u]; \
            float4 v[U]; \
            _Pragma("unroll") for (int u = 0; u < U; u++) v[u] = f4[si[u] * 32 + lane]; \
            _Pragma("unroll") for (int u = 0; u < U; u++) { \
                float4 t = v[u]; \
                t.x = fmaxf(fmaf(t.x, sc4.x, sh4.x), 0.f); \
                t.y = fmaxf(fmaf(t.y, sc4.y, sh4.y), 0.f); \
                t.z = fmaxf(fmaf(t.z, sc4.z, sh4.z), 0.f); \
                t.w = fmaxf(fmaf(t.w, sc4.w, sh4.w), 0.f); \
                acc.x += t.x; acc.y += t.y; acc.z += t.z; acc.w += t.w; \
            } \
            j += U; \
        }
        for (; j + 8 <= cnt;) GB(8)
        if (j + 4 <= cnt) GB(4)
        if (j + 2 <= cnt) GB(2)
        if (j + 1 <= cnt) GB(1)
#undef GB
        float scv = g_inv_deg[gw];
        ((float4*)out)[gw * 32 + lane] =
            make_float4(acc.x * scv, acc.y * scv, acc.z * scv, acc.w * scv);
    }
}

// ================= weight prep =================
__global__ void k_prep_w(const float* __restrict__ Wself, const float* __restrict__ Wnbr) {
    int inst = blockIdx.x;
    const float* ws = Wself + (size_t)inst * DD * DD;
    const float* wn = Wnbr  + (size_t)inst * DD * DD;
    char* dh = g_wt_hi[inst];
    char* dl = g_wt_lo[inst];
    for (int idx = threadIdx.x; idx < 256 * 128; idx += blockDim.x) {
        int n = idx & 127;
        int k = idx >> 7;
        float w = (k < 128) ? ws[k * 128 + n] : wn[(k - 128) * 128 + n];
        __nv_bfloat16 hi = __float2bfloat16(w);
        __nv_bfloat16 lo = __float2bfloat16(w - __bfloat162float(hi));
        int chunk = k >> 7;
        int kk = k & 127;
        int off = chunk * 32768 + swz(n, kk * 2);
        *(__nv_bfloat16*)(dh + off) = hi;
        *(__nv_bfloat16*)(dl + off) = lo;
    }
}

// ================= A-tile conversion (CNT4 float4 groups, lo plane at +LOOFF) =========
template <bool BN, int NT, int CNT4, int LOOFF>
__device__ __forceinline__ void convert_A(char* sm, int base, const float* __restrict__ src,
                                          const float* __restrict__ scale,
                                          const float* __restrict__ shift,
                                          int n0, int tid)
{
    for (int idx = tid; idx < CNT4; idx += NT) {
        int r  = idx >> 5;
        int kg = idx & 31;
        int n  = n0 + r;
        float4 v = make_float4(0.f, 0.f, 0.f, 0.f);
        if (n < NN) v = ((const float4*)src)[n * 32 + kg];
        if (BN) {
            float4 sc = ((const float4*)scale)[kg];
            float4 sh = ((const float4*)shift)[kg];
            v.x = fmaxf(fmaf(v.x, sc.x, sh.x), 0.f);
            v.y = fmaxf(fmaf(v.y, sc.y, sh.y), 0.f);
            v.z = fmaxf(fmaf(v.z, sc.z, sh.z), 0.f);
            v.w = fmaxf(fmaf(v.w, sc.w, sh.w), 0.f);
        }
        int off = swz(r, kg * 8);
        __nv_bfloat16 hx = __float2bfloat16(v.x);
        __nv_bfloat16 hy = __float2bfloat16(v.y);
        __nv_bfloat16 hz = __float2bfloat16(v.z);
        __nv_bfloat16 hw = __float2bfloat16(v.w);
        __nv_bfloat16 lx = __float2bfloat16(v.x - __bfloat162float(hx));
        __nv_bfloat16 ly = __float2bfloat16(v.y - __bfloat162float(hy));
        __nv_bfloat16 lz = __float2bfloat16(v.z - __bfloat162float(hz));
        __nv_bfloat16 lw = __float2bfloat16(v.w - __bfloat162float(hw));
        uint2 ph, pl;
        ph.x = ((uint32_t)__bfloat16_as_ushort(hy) << 16) | __bfloat16_as_ushort(hx);
        ph.y = ((uint32_t)__bfloat16_as_ushort(hw) << 16) | __bfloat16_as_ushort(hz);
        pl.x = ((uint32_t)__bfloat16_as_ushort(ly) << 16) | __bfloat16_as_ushort(lx);
        pl.y = ((uint32_t)__bfloat16_as_ushort(lw) << 16) | __bfloat16_as_ushort(lz);
        *(uint2*)(sm + base + off) = ph;
        *(uint2*)(sm + base + LOOFF + off) = pl;
    }
}

// ================= MMA passes =================
struct MmaCtx { int lrowA, lkgA, lnB, lkgB, wr, wc; };

template <bool DUAL>
__device__ __forceinline__ void mma_pass(uint32_t smb, int ahbase, int albase, int bbase,
                                         const MmaCtx& c, float acc[2][4][4]) {
#pragma unroll
    for (int ks = 0; ks < 8; ks++) {
        uint32_t ah[2][4], al[2][4], bb[2][4];
#pragma unroll
        for (int at = 0; at < 2; at++) {
            int row = c.wr * 32 + at * 16 + c.lrowA;
            int kb  = (ks * 2 + c.lkgA) * 16;
            uint32_t off = (uint32_t)swz(row, kb);
            ldsm4(ah[at], smb + ahbase + off);
            if (DUAL) ldsm4(al[at], smb + albase + off);
        }
#pragma unroll
        for (int bp = 0; bp < 2; bp++) {
            int nrow = c.wc * 32 + bp * 16 + c.lnB;
            int kb   = (ks * 2 + c.lkgB) * 16;
            ldsm4(bb[bp], smb + bbase + (uint32_t)swz(nrow, kb));
        }
#pragma unroll
        for (int at = 0; at < 2; at++)
#pragma unroll
            for (int bp = 0; bp < 2; bp++)
#pragma unroll
                for (int hf = 0; hf < 2; hf++)
                    mma16816(acc[at][bp * 2 + hf], ah[at], &bb[bp][hf * 2]);
        if (DUAL) {
#pragma unroll
            for (int at = 0; at < 2; at++)
#pragma unroll
                for (int bp = 0; bp < 2; bp++)
#pragma unroll
                    for (int hf = 0; hf < 2; hf++)
                        mma16816(acc[at][bp * 2 + hf], al[at], &bb[bp][hf * 2]);
        }
    }
}

__device__ __forceinline__ void mma_pass3(uint32_t smb, int ahbase, int albase,
                                          int bhbase, int blbase,
                                          const MmaCtx& c, float acc[2][4][4]) {
#pragma unroll
    for (int ks = 0; ks < 8; ks++) {
        uint32_t ah[2][4], al[2][4], bh[2][4], bl[2][4];
#pragma unroll
        for (int at = 0; at < 2; at++) {
            int row = c.wr * 32 + at * 16 + c.lrowA;
            int kb  = (ks * 2 + c.lkgA) * 16;
            uint32_t off = (uint32_t)swz(row, kb);
            ldsm4(ah[at], smb + ahbase + off);
            ldsm4(al[at], smb + albase + off);
        }
#pragma unroll
        for (int bp = 0; bp < 2; bp++) {
            int nrow = c.wc * 32 + bp * 16 + c.lnB;
            int kb   = (ks * 2 + c.lkgB) * 16;
            uint32_t off = (uint32_t)swz(nrow, kb);
            ldsm4(bh[bp], smb + bhbase + off);
            ldsm4(bl[bp], smb + blbase + off);
        }
#pragma unroll
        for (int at = 0; at < 2; at++)
#pragma unroll
            for (int bp = 0; bp < 2; bp++)
#pragma unroll
                for (int hf = 0; hf < 2; hf++)
                    mma16816(acc[at][bp * 2 + hf], ah[at], &bh[bp][hf * 2]);
#pragma unroll
        for (int at = 0; at < 2; at++)
#pragma unroll
            for (int bp = 0; bp < 2; bp++)
#pragma unroll
                for (int hf = 0; hf < 2; hf++)
                    mma16816(acc[at][bp * 2 + hf], ah[at], &bl[bp][hf * 2]);
#pragma unroll
        for (int at = 0; at < 2; at++)
#pragma unroll
            for (int bp = 0; bp < 2; bp++)
#pragma unroll
                for (int hf = 0; hf < 2; hf++)
                    mma16816(acc[at][bp * 2 + hf], al[at], &bh[bp][hf * 2]);
    }
}

// gemm0 B tile: t (0..31): e=t>>2, sub=t&3, chunk=sub>>1, which=sub&1; buf = t&1
__device__ __forceinline__ void issue_b0(uint32_t smb, uint32_t bufbase,
                                         const char* wth_all, const char* wtl_all,
                                         int t, int tid) {
    int e = t >> 2, sub = t & 3, chunk = sub >> 1, which = sub & 1;
    const char* src = (which ? wtl_all : wth_all)
                    + (size_t)(e * 2) * 65536 + chunk * 32768;
    uint32_t dst = smb + bufbase + (uint32_t)(t & 1) * 32768;
#pragma unroll
    for (int i = 0; i < 2048; i += 512) {
        int idx = tid + i;
        cp16(dst + idx * 16, src + idx * 16);
    }
    CP_COMMIT();
}

// gemm1 B tile: buf fixed by which (0=hi, 1=lo)
__device__ __forceinline__ void issue_b1(uint32_t smb, uint32_t bufbase,
                                         const char* wth, const char* wtl,
                                         int chunk, int which, int tid) {
    const char* src = (which ? wtl : wth) + chunk * 32768;
    uint32_t dst = smb + bufbase + (uint32_t)which * 32768;
#pragma unroll
    for (int i = 0; i < 2048; i += 256) {
        int idx = tid + i;
        cp16(dst + idx * 16, src + idx * 16);
    }
    CP_COMMIT();
}

// ================= batched layer-0 GEMM (512 thr, 1 CTA/SM, pipelined B) ==============
#define G0_B 131072
#define G0_TOTAL 196608

__global__ void __launch_bounds__(512, 1)
k_gemm0_all(const float* __restrict__ x, const float* __restrict__ agg0,
            const char* __restrict__ wth_all, const char* __restrict__ wtl_all,
            const float* __restrict__ bprm, float* __restrict__ h_all)
{
    extern __shared__ char sm[];
    uint32_t smb = smem_u32(sm);
    int tid = threadIdx.x, wid = tid >> 5, lane = tid & 31;
    int n0 = blockIdx.x * 128;
    MmaCtx c;
    c.wr = wid & 3; c.wc = wid >> 2;
    c.lrowA = lane & 15; c.lkgA = lane >> 4;
    c.lnB = (lane & 7) + ((lane >> 4) << 3); c.lkgB = (lane >> 3) & 1;
    int trow = lane >> 2, tc2 = lane & 3;

    convert_A<false, 512, 4096, 32768>(sm, 0,     x,    nullptr, nullptr, n0, tid);
    convert_A<false, 512, 4096, 32768>(sm, 65536, agg0, nullptr, nullptr, n0, tid);

    issue_b0(smb, G0_B, wth_all, wtl_all, 0, tid);

    float acc[2][4][4];
#pragma unroll
    for (int a = 0; a < 2; a++)
#pragma unroll
        for (int b = 0; b < 4; b++)
#pragma unroll
            for (int q = 0; q < 4; q++) acc[a][b][q] = 0.f;

    for (int e = 0; e < NEXP; e++) {
#pragma unroll
        for (int sub = 0; sub < 4; sub++) {
            int t = e * 4 + sub;
            if (t + 1 < 32) {
                issue_b0(smb, G0_B, wth_all, wtl_all, t + 1, tid);
                CP_WAIT1();
            } else {
                CP_WAIT0();
            }
            __syncthreads();
            int ab = (sub >> 1) * 65536;
            int bbase = G0_B + (t & 1) * 32768;
            if ((sub & 1) == 0)
                mma_pass<true>(smb, ab, ab + 32768, bbase, c, acc);
            else
                mma_pass<false>(smb, ab, 0, bbase, c, acc);

            if (sub == 3) {
                const float* be = bprm + (size_t)(e * 2) * DD;
                float2* o = (float2*)(h_all + (size_t)e * NN * DD);
#pragma unroll
                for (int bt = 0; bt < 4; bt++) {
                    int col = c.wc * 32 + bt * 8 + tc2 * 2;
                    float bx = be[col], by = be[col + 1];
                    float sx = 0.f, sy = 0.f, qx = 0.f, qy = 0.f;
#pragma unroll
                    for (int at = 0; at < 2; at++) {
                        int r0 = n0 + c.wr * 32 + at * 16 + trow;
                        float v0x = acc[at][bt][0] + bx, v0y = acc[at][bt][1] + by;
                        float v1x = acc[at][bt][2] + bx, v1y = acc[at][bt][3] + by;
                        if (r0 < NN) {
                            o[r0 * 64 + (col >> 1)] = make_float2(v0x, v0y);
                            sx += v0x; sy += v0y; qx += v0x * v0x; qy += v0y * v0y;
                        }
                        if (r0 + 8 < NN) {
                            o[(r0 + 8) * 64 + (col >> 1)] = make_float2(v1x, v1y);
                            sx += v1x; sy += v1y; qx += v1x * v1x; qy += v1y * v1y;
                        }
                    }
#pragma unroll
                    for (int off = 4; off < 32; off <<= 1) {
                        sx += __shfl_xor_sync(0xFFFFFFFF, sx, off);
                        sy += __shfl_xor_sync(0xFFFFFFFF, sy, off);
                        qx += __shfl_xor_sync(0xFFFFFFFF, qx, off);
                        qy += __shfl_xor_sync(0xFFFFFFFF, qy, off);
                    }
                    if (lane < 4) {
                        atomicAdd(&g_stats_s[e * DD + col], sx);
                        atomicAdd(&g_stats_s[e * DD + col + 1], sy);
                        atomicAdd(&g_stats_q[e * DD + col], qx);
                        atomicAdd(&g_stats_q[e * DD + col + 1], qy);
                    }
                }
#pragma unroll
                for (int a = 0; a < 2; a++)
#pragma unroll
                    for (int b = 0; b < 4; b++)
#pragma unroll
                        for (int q = 0; q < 4; q++) acc[a][b][q] = 0.f;
            }
            __syncthreads();
        }
    }
}

// ================= finalize BN =================
__global__ void k_finalize(const float* __restrict__ gamma, const float* __restrict__ beta) {
    int i = threadIdx.x + blockIdx.x * blockDim.x;
    if (i >= NEXP * DD) return;
    const float invn = 1.0f / (float)NN;
    float m = g_stats_s[i] * invn;
    float var = g_stats_q[i] * invn - m * m;
    float r = rsqrtf(var + EPSV);
    float sc = gamma[i] * r;
    g_scale[i] = sc;
    g_shift[i] = beta[i] - m * sc;
}

// ================= per-expert layer-1 GEMM: M=64 tile, 256 thr, 2 CTAs/SM =============
#define G1_ALO 16384
#define G1_B   32768
#define G1_TOTAL 98304

__global__ void __launch_bounds__(256, 2)
k_gemm1_one(const float* __restrict__ he, const float* __restrict__ ae,
            const char* __restrict__ wth, const char* __restrict__ wtl,
            const float* __restrict__ be,
            const float* __restrict__ scale, const float* __restrict__ shift,
            float* __restrict__ oe)
{
    extern __shared__ char sm[];
    uint32_t smb = smem_u32(sm);
    int tid = threadIdx.x, wid = tid >> 5, lane = tid & 31;
    int n0 = blockIdx.x * 64;
    MmaCtx c;
    c.wr = wid & 1; c.wc = wid >> 1;
    c.lrowA = lane & 15; c.lkgA = lane >> 4;
    c.lnB = (lane & 7) + ((lane >> 4) << 3); c.lkgB = (lane >> 3) & 1;
    int trow = lane >> 2, tc2 = lane & 3;

    issue_b1(smb, G1_B, wth, wtl, 0, 0, tid);
    issue_b1(smb, G1_B, wth, wtl, 0, 1, tid);

    float acc[2][4][4];
#pragma unroll
    for (int a = 0; a < 2; a++)
#pragma unroll
        for (int b = 0; b < 4; b++)
#pragma unroll
            for (int q = 0; q < 4; q++) acc[a][b][q] = 0.f;

#pragma unroll
    for (int chunk = 0; chunk < 2; chunk++) {
        if (chunk == 0)
            convert_A<true, 256, 2048, G1_ALO>(sm, 0, he, scale, shift, n0, tid);
        else
            convert_A<false, 256, 2048, G1_ALO>(sm, 0, ae, nullptr, nullptr, n0, tid);
        CP_WAIT0();
        __syncthreads();
        mma_pass3(smb, 0, G1_ALO, G1_B, G1_B + 32768, c, acc);
        __syncthreads();
        if (chunk == 0) {
            issue_b1(smb, G1_B, wth, wtl, 1, 0, tid);
            issue_b1(smb, G1_B, wth, wtl, 1, 1, tid);
        }
    }

    float2* o = (float2*)oe;
#pragma unroll
    for (int at = 0; at < 2; at++)
#pragma unroll
        for (int bt = 0; bt < 4; bt++) {
            int col = c.wc * 32 + bt * 8 + tc2 * 2;
            float bx = be[col], by = be[col + 1];
            int r0 = n0 + c.wr * 32 + at * 16 + trow;
            if (r0 < NN)
                o[r0 * 64 + (col >> 1)] =
                    make_float2(acc[at][bt][0] + bx, acc[at][bt][1] + by);
            if (r0 + 8 < NN)
                o[(r0 + 8) * 64 + (col >> 1)] =
                    make_float2(acc[at][bt][2] + bx, acc[at][bt][3] + by);
        }
}

// ================= final interleave [8][N][128] -> [N][128][8] =================
__global__ void k_interleave(float* __restrict__ out) {
    int idx = blockIdx.x * blockDim.x + threadIdx.x;
    if (idx >= NN * DD) return;
    float v[8];
#pragma unroll
    for (int e = 0; e < 8; e++) v[e] = g_out_tmp[(size_t)e * (NN * DD) + idx];
    float4* o = (float4*)out + (size_t)idx * 2;
    o[0] = make_float4(v[0], v[1], v[2], v[3]);
    o[1] = make_float4(v[4], v[5], v[6], v[7]);
}

// ================= launch =================
extern "C" void kernel_launch(void* const* d_in, const int* in_sizes, int n_in,
                              void* d_out, int out_size)
{
    const float* x      = (const float*)d_in[0];
    const int*   ei32   = (const int*)d_in[1];
    const float* W_self = (const float*)d_in[2];
    const float* W_nbr  = (const float*)d_in[3];
    const float* bprm   = (const float*)d_in[4];
    const float* gamma  = (const float*)d_in[5];
    const float* beta   = (const float*)d_in[6];
    float*       out    = (float*)d_out;

    cudaFuncSetAttribute(k_gemm0_all, cudaFuncAttributeMaxDynamicSharedMemorySize, G0_TOTAL);
    cudaFuncSetAttribute(k_gemm1_one, cudaFuncAttributeMaxDynamicSharedMemorySize, G1_TOTAL);

    float *agg0, *agg1, *hall, *otmp, *scl, *shf;
    char *wth, *wtl;
    cudaGetSymbolAddress((void**)&agg0, g_agg0);
    cudaGetSymbolAddress((void**)&agg1, g_agg1_all);
    cudaGetSymbolAddress((void**)&hall, g_h_all);
    cudaGetSymbolAddress((void**)&otmp, g_out_tmp);
    cudaGetSymbolAddress((void**)&scl,  g_scale);
    cudaGetSymbolAddress((void**)&shf,  g_shift);
    cudaGetSymbolAddress((void**)&wth,  g_wt_hi);
    cudaGetSymbolAddress((void**)&wtl,  g_wt_lo);

    const int NB0 = (NN + 127) / 128;   // 782
    const int NB1 = (NN + 63) / 64;     // 1563
    cudaStream_t s0 = 0;
    cudaStream_t s2 = g_ss.s2;

    // fork: side stream joins the capture via event
    k_init<<<1, 1024, 0, s0>>>(ei32);
    cudaEventRecord(g_ss.evFork, s0);
    cudaStreamWaitEvent(s2, g_ss.evFork, 0);

    // prep_w (s2) overlaps csr_agg0 (s0)
    k_prep_w<<<16, 256, 0, s2>>>(W_self, W_nbr);
    cudaEventRecord(g_ss.evPrep, s2);
    k_csr_agg0<<<NBLK, 256, 0, s0>>>(ei32, x, agg0);

    // gemm0 needs both
    cudaStreamWaitEvent(s0, g_ss.evPrep, 0);
    k_gemm0_all<<<NB0, 512, G0_TOTAL, s0>>>(x, agg0, wth, wtl, bprm, hall);
    k_finalize<<<1, 1024, 0, s0>>>(gamma, beta);

    // pipelined per-expert: agg(e) on s0 (persistent, 25% thread slots),
    // gemm1(e) on s2 co-scheduled.
    for (int e = 0; e < NEXP; e++) {
        const float* he = hall + (size_t)e * NN * DD;
        float*       ae = agg1 + (size_t)e * NN * DD;
        k_agg<<<AGG_NBLK, 256, 0, s0>>>(he, ae, scl + e * DD, shf + e * DD);
        cudaEventRecord(g_ss.evA[e], s0);
        cudaStreamWaitEvent(s2, g_ss.evA[e], 0);
        k_gemm1_one<<<NB1, 256, G1_TOTAL, s2>>>(
            he, ae,
            (const char*)(wth + (size_t)(e * 2 + 1) * 65536),
            (const char*)(wtl + (size_t)(e * 2 + 1) * 65536),
            bprm + (size_t)(e * 2 + 1) * DD,
            scl + e * DD, shf + e * DD,
            otmp + (size_t)e * NN * DD);
    }

    // join: interleave after last gemm1
    cudaEventRecord(g_ss.evG, s2);
    cudaStreamWaitEvent(s0, g_ss.evG, 0);
    k_interleave<<<(NN * DD) / 256, 256, 0, s0>>>(out);
}

// round 16
// speedup vs baseline: 1.5123x; 1.5123x over previous
#include <cuda_runtime.h>
#include <cuda_bf16.h>
#include <cstdint>

#define NN 100000
#define EE 1600000
#define DD 128
#define NEXP 8
#define EPSV 1e-5f
#define NBLK 592
#define GT (NBLK * 256)

// ================= scratch (static device globals) =================
__device__ int   g_deg[NN];
__device__ int   g_off[NN];
__device__ int   g_cur[NN];
__device__ float g_inv_deg[NN];
__device__ int   g_srcs[EE];
__device__ int   g_bsum2[NBLK];
__device__ int   g_barrier[8];
__device__ int   g_is64;
__device__ float g_agg0[NN * DD];
__device__ float g_stats_s[NEXP * DD];
__device__ float g_stats_q[NEXP * DD];
__device__ float g_scale[NEXP * DD];
__device__ float g_shift[NEXP * DD];
__device__ char  g_wt_hi[16][65536];     // per (e,l): 2 chunks x [128n][128k] bf16, swizzled
__device__ char  g_wt_lo[16][65536];
__device__ float g_h_all[(size_t)NEXP * NN * DD];     // [8][N][128] pre-BN layer-0 h
__device__ float g_agg1_all[(size_t)NEXP * NN * DD];  // [8][N][128]
__device__ float g_out_tmp[(size_t)NEXP * NN * DD];   // [8][N][128] layer-1 outputs

// ================= host-side streams/events (pre-main init; host objects only) ========
struct SideStream {
    cudaStream_t s2;
    cudaEvent_t evFork, evPrep, evG;
    cudaEvent_t evA[NEXP];
    SideStream() {
        int lo = 0, hi = 0;
        cudaDeviceGetStreamPriorityRange(&lo, &hi);   // hi = highest priority (most negative)
        cudaStreamCreateWithPriority(&s2, cudaStreamNonBlocking, hi);
        cudaEventCreateWithFlags(&evFork, cudaEventDisableTiming);
        cudaEventCreateWithFlags(&evPrep, cudaEventDisableTiming);
        cudaEventCreateWithFlags(&evG, cudaEventDisableTiming);
        for (int i = 0; i < NEXP; i++)
            cudaEventCreateWithFlags(&evA[i], cudaEventDisableTiming);
    }
};
static SideStream g_ss;

// ================= device helpers =================
__device__ __forceinline__ uint32_t smem_u32(const void* p) {
    uint32_t a;
    asm("{ .reg .u64 t; cvta.to.shared.u64 t, %1; cvt.u32.u64 %0, t; }" : "=r"(a) : "l"(p));
    return a;
}
__device__ __forceinline__ void ldsm4(uint32_t* r, uint32_t addr) {
    asm volatile("ldmatrix.sync.aligned.m8n8.x4.shared.b16 {%0,%1,%2,%3}, [%4];"
        : "=r"(r[0]), "=r"(r[1]), "=r"(r[2]), "=r"(r[3]) : "r"(addr));
}
__device__ __forceinline__ void mma16816(float* d, const uint32_t* a, const uint32_t* b) {
    asm volatile("mma.sync.aligned.m16n8k16.row.col.f32.bf16.bf16.f32 "
        "{%0,%1,%2,%3}, {%4,%5,%6,%7}, {%8,%9}, {%0,%1,%2,%3};"
        : "+f"(d[0]), "+f"(d[1]), "+f"(d[2]), "+f"(d[3])
        : "r"(a[0]), "r"(a[1]), "r"(a[2]), "r"(a[3]), "r"(b[0]), "r"(b[1]));
}
__device__ __forceinline__ int swz(int row, int kbyte) {
    return row * 256 + ((((kbyte >> 4) ^ (row & 7)) << 4) | (kbyte & 15));
}
__device__ __forceinline__ void cp16(uint32_t dst, const void* src) {
    asm volatile("cp.async.cg.shared.global [%0], [%1], 16;" :: "r"(dst), "l"(src));
}
#define CP_COMMIT() asm volatile("cp.async.commit_group;" ::: "memory")
#define CP_WAIT1() asm volatile("cp.async.wait_group 1;" ::: "memory")
#define CP_WAIT0() asm volatile("cp.async.wait_group 0;" ::: "memory")

// ================= software grid barrier =================
__device__ __forceinline__ void grid_bar(int slot) {
    __syncthreads();
    if (threadIdx.x == 0) {
        __threadfence();
        int arrived = atomicAdd(&g_barrier[slot], 1) + 1;
        if (arrived < NBLK) {
            while (((volatile int*)g_barrier)[slot] < NBLK) { }
        }
        __threadfence();
    }
    __syncthreads();
}

// ================= init =================
__global__ void k_init(const int* __restrict__ ei32) {
    int t = threadIdx.x;
    if (t < 8) g_barrier[t] = 0;
    for (int i = t; i < NEXP * DD; i += 1024) { g_stats_s[i] = 0.f; g_stats_q[i] = 0.f; }
    if (t == 0) {
        int hz = 1;
        for (int i = 0; i < 64; i++)
            if (ei32[2 * i + 1] != 0) { hz = 0; break; }
        g_is64 = hz;
    }
}

// ================= fused CSR build + layer-0 aggregation =================
__global__ void __launch_bounds__(256)
k_csr_agg0(const int* __restrict__ ei32, const float* __restrict__ x,
           float* __restrict__ agg0)
{
    int tid = threadIdx.x, b = blockIdx.x;
    int gt = b * 256 + tid;
    __shared__ int s[256];
    __shared__ int bs[NBLK];

    for (int i = gt; i < NN; i += GT) g_deg[i] = 0;
    grid_bar(0);

    int is64 = g_is64;
    for (int i = gt; i < EE; i += GT) {
        int d = is64 ? ei32[2 * (EE + i)] : ei32[EE + i];
        if ((unsigned)d < NN) atomicAdd(&g_deg[d], 1);
    }
    grid_bar(1);

    int base0 = gt * 2;
    int d0 = (base0     < NN) ? g_deg[base0]     : 0;
    int d1 = (base0 + 1 < NN) ? g_deg[base0 + 1] : 0;
    int tsum = d0 + d1;
    s[tid] = tsum;
    __syncthreads();
    for (int o = 1; o < 256; o <<= 1) {
        int a = (tid >= o) ? s[tid - o] : 0;
        __syncthreads();
        s[tid] += a;
        __syncthreads();
    }
    if (tid == 255) g_bsum2[b] = s[255];
    grid_bar(2);

    if (b == 0) {
        for (int i = tid; i < NBLK; i += 256) bs[i] = g_bsum2[i];
        __syncthreads();
        if (tid == 0) {
            int run = 0;
            for (int i = 0; i < NBLK; i++) { int v = bs[i]; bs[i] = run; run += v; }
        }
        __syncthreads();
        for (int i = tid; i < NBLK; i += 256) g_bsum2[i] = bs[i];
    }
    grid_bar(3);

    {
        int tbase = g_bsum2[b] + (s[tid] - tsum);
        if (base0 < NN) {
            g_off[base0] = tbase;
            g_cur[base0] = tbase;
            g_inv_deg[base0] = 1.0f / (float)(d0 > 0 ? d0 : 1);
        }
        if (base0 + 1 < NN) {
            int o1 = tbase + d0;
            g_off[base0 + 1] = o1;
            g_cur[base0 + 1] = o1;
            g_inv_deg[base0 + 1] = 1.0f / (float)(d1 > 0 ? d1 : 1);
        }
    }
    grid_bar(4);

    for (int i = gt; i < EE; i += GT) {
        int d  = is64 ? ei32[2 * (EE + i)] : ei32[EE + i];
        int sv = is64 ? ei32[2 * i]        : ei32[i];
        if ((unsigned)d < NN && (unsigned)sv < NN) {
            int pos = atomicAdd(&g_cur[d], 1);
            g_srcs[pos] = sv;
        }
    }
    grid_bar(5);

    {
        int gw = gt >> 5, lane = tid & 31;
        const int NW = NBLK * 8;
        const float4* f4 = (const float4*)x;
        for (int node = gw; node < NN; node += NW) {
            int start = g_off[node];
            int cnt   = g_cur[node] - start;
            float4 acc = make_float4(0.f, 0.f, 0.f, 0.f);
            int j = 0;
#define GB(U) \
            { \
                int si[U]; \
                _Pragma("unroll") for (int u = 0; u < U; u++) si[u] = g_srcs[start + j + u]; \
                float4 v[U]; \
                _Pragma("unroll") for (int u = 0; u < U; u++) v[u] = f4[si[u] * 32 + lane]; \
                _Pragma("unroll") for (int u = 0; u < U; u++) { \
                    acc.x += v[u].x; acc.y += v[u].y; acc.z += v[u].z; acc.w += v[u].w; \
                } \
                j += U; \
            }
            for (; j + 8 <= cnt;) GB(8)
            if (j + 4 <= cnt) GB(4)
            if (j + 2 <= cnt) GB(2)
            if (j + 1 <= cnt) GB(1)
#undef GB
            float scv = g_inv_deg[node];
            ((float4*)agg0)[node * 32 + lane] =
                make_float4(acc.x * scv, acc.y * scv, acc.z * scv, acc.w * scv);
        }
    }
}

// ================= per-expert layer-1 aggregation (BN+ReLU on gather) =================
__global__ void k_agg(const float* __restrict__ feat, float* __restrict__ out,
                      const float* __restrict__ scale, const float* __restrict__ shift)
{
    int gw = (blockIdx.x * blockDim.x + threadIdx.x) >> 5;
    int lane = threadIdx.x & 31;
    if (gw >= NN) return;
    int start = g_off[gw];
    int cnt   = g_cur[gw] - start;
    const float4* f4 = (const float4*)feat;
    float4 sc4 = ((const float4*)scale)[lane];
    float4 sh4 = ((const float4*)shift)[lane];
    float4 acc = make_float4(0.f, 0.f, 0.f, 0.f);
    int j = 0;
#define GB(U) \
    { \
        int si[U]; \
        _Pragma("unroll") for (int u = 0; u < U; u++) si[u] = g_srcs[start + j + u]; \
        float4 v[U]; \
        _Pragma("unroll") for (int u = 0; u < U; u++) v[u] = f4[si[u] * 32 + lane]; \
        _Pragma("unroll") for (int u = 0; u < U; u++) { \
            float4 t = v[u]; \
            t.x = fmaxf(fmaf(t.x, sc4.x, sh4.x), 0.f); \
            t.y = fmaxf(fmaf(t.y, sc4.y, sh4.y), 0.f); \
            t.z = fmaxf(fmaf(t.z, sc4.z, sh4.z), 0.f); \
            t.w = fmaxf(fmaf(t.w, sc4.w, sh4.w), 0.f); \
            acc.x += t.x; acc.y += t.y; acc.z += t.z; acc.w += t.w; \
        } \
        j += U; \
    }
    for (; j + 8 <= cnt;) GB(8)
    if (j + 4 <= cnt) GB(4)
    if (j + 2 <= cnt) GB(2)
    if (j + 1 <= cnt) GB(1)
#undef GB
    float scv = g_inv_deg[gw];
    ((float4*)out)[gw * 32 + lane] =
        make_float4(acc.x * scv, acc.y * scv, acc.z * scv, acc.w * scv);
}

// ================= weight prep =================
__global__ void k_prep_w(const float* __restrict__ Wself, const float* __restrict__ Wnbr) {
    int inst = blockIdx.x;
    const float* ws = Wself + (size_t)inst * DD * DD;
    const float* wn = Wnbr  + (size_t)inst * DD * DD;
    char* dh = g_wt_hi[inst];
    char* dl = g_wt_lo[inst];
    for (int idx = threadIdx.x; idx < 256 * 128; idx += blockDim.x) {
        int n = idx & 127;
        int k = idx >> 7;
        float w = (k < 128) ? ws[k * 128 + n] : wn[(k - 128) * 128 + n];
        __nv_bfloat16 hi = __float2bfloat16(w);
        __nv_bfloat16 lo = __float2bfloat16(w - __bfloat162float(hi));
        int chunk = k >> 7;
        int kk = k & 127;
        int off = chunk * 32768 + swz(n, kk * 2);
        *(__nv_bfloat16*)(dh + off) = hi;
        *(__nv_bfloat16*)(dl + off) = lo;
    }
}

// ================= A-tile conversion (CNT4 float4 groups, lo plane at +LOOFF) =========
template <bool BN, int NT, int CNT4, int LOOFF>
__device__ __forceinline__ void convert_A(char* sm, int base, const float* __restrict__ src,
                                          const float* __restrict__ scale,
                                          const float* __restrict__ shift,
                                          int n0, int tid)
{
    for (int idx = tid; idx < CNT4; idx += NT) {
        int r  = idx >> 5;
        int kg = idx & 31;
        int n  = n0 + r;
        float4 v = make_float4(0.f, 0.f, 0.f, 0.f);
        if (n < NN) v = ((const float4*)src)[n * 32 + kg];
        if (BN) {
            float4 sc = ((const float4*)scale)[kg];
            float4 sh = ((const float4*)shift)[kg];
            v.x = fmaxf(fmaf(v.x, sc.x, sh.x), 0.f);
            v.y = fmaxf(fmaf(v.y, sc.y, sh.y), 0.f);
            v.z = fmaxf(fmaf(v.z, sc.z, sh.z), 0.f);
            v.w = fmaxf(fmaf(v.w, sc.w, sh.w), 0.f);
        }
        int off = swz(r, kg * 8);
        __nv_bfloat16 hx = __float2bfloat16(v.x);
        __nv_bfloat16 hy = __float2bfloat16(v.y);
        __nv_bfloat16 hz = __float2bfloat16(v.z);
        __nv_bfloat16 hw = __float2bfloat16(v.w);
        __nv_bfloat16 lx = __float2bfloat16(v.x - __bfloat162float(hx));
        __nv_bfloat16 ly = __float2bfloat16(v.y - __bfloat162float(hy));
        __nv_bfloat16 lz = __float2bfloat16(v.z - __bfloat162float(hz));
        __nv_bfloat16 lw = __float2bfloat16(v.w - __bfloat162float(hw));
        uint2 ph, pl;
        ph.x = ((uint32_t)__bfloat16_as_ushort(hy) << 16) | __bfloat16_as_ushort(hx);
        ph.y = ((uint32_t)__bfloat16_as_ushort(hw) << 16) | __bfloat16_as_ushort(hz);
        pl.x = ((uint32_t)__bfloat16_as_ushort(ly) << 16) | __bfloat16_as_ushort(lx);
        pl.y = ((uint32_t)__bfloat16_as_ushort(lw) << 16) | __bfloat16_as_ushort(lz);
        *(uint2*)(sm + base + off) = ph;
        *(uint2*)(sm + base + LOOFF + off) = pl;
    }
}

// ================= MMA passes =================
struct MmaCtx { int lrowA, lkgA, lnB, lkgB, wr, wc; };

template <bool DUAL>
__device__ __forceinline__ void mma_pass(uint32_t smb, int ahbase, int albase, int bbase,
                                         const MmaCtx& c, float acc[2][4][4]) {
#pragma unroll
    for (int ks = 0; ks < 8; ks++) {
        uint32_t ah[2][4], al[2][4], bb[2][4];
#pragma unroll
        for (int at = 0; at < 2; at++) {
            int row = c.wr * 32 + at * 16 + c.lrowA;
            int kb  = (ks * 2 + c.lkgA) * 16;
            uint32_t off = (uint32_t)swz(row, kb);
            ldsm4(ah[at], smb + ahbase + off);
            if (DUAL) ldsm4(al[at], smb + albase + off);
        }
#pragma unroll
        for (int bp = 0; bp < 2; bp++) {
            int nrow = c.wc * 32 + bp * 16 + c.lnB;
            int kb   = (ks * 2 + c.lkgB) * 16;
            ldsm4(bb[bp], smb + bbase + (uint32_t)swz(nrow, kb));
        }
#pragma unroll
        for (int at = 0; at < 2; at++)
#pragma unroll
            for (int bp = 0; bp < 2; bp++)
#pragma unroll
                for (int hf = 0; hf < 2; hf++)
                    mma16816(acc[at][bp * 2 + hf], ah[at], &bb[bp][hf * 2]);
        if (DUAL) {
#pragma unroll
            for (int at = 0; at < 2; at++)
#pragma unroll
                for (int bp = 0; bp < 2; bp++)
#pragma unroll
                    for (int hf = 0; hf < 2; hf++)
                        mma16816(acc[at][bp * 2 + hf], al[at], &bb[bp][hf * 2]);
        }
    }
}

__device__ __forceinline__ void mma_pass3(uint32_t smb, int ahbase, int albase,
                                          int bhbase, int blbase,
                                          const MmaCtx& c, float acc[2][4][4]) {
#pragma unroll
    for (int ks = 0; ks < 8; ks++) {
        uint32_t ah[2][4], al[2][4], bh[2][4], bl[2][4];
#pragma unroll
        for (int at = 0; at < 2; at++) {
            int row = c.wr * 32 + at * 16 + c.lrowA;
            int kb  = (ks * 2 + c.lkgA) * 16;
            uint32_t off = (uint32_t)swz(row, kb);
            ldsm4(ah[at], smb + ahbase + off);
            ldsm4(al[at], smb + albase + off);
        }
#pragma unroll
        for (int bp = 0; bp < 2; bp++) {
            int nrow = c.wc * 32 + bp * 16 + c.lnB;
            int kb   = (ks * 2 + c.lkgB) * 16;
            uint32_t off = (uint32_t)swz(nrow, kb);
            ldsm4(bh[bp], smb + bhbase + off);
            ldsm4(bl[bp], smb + blbase + off);
        }
#pragma unroll
        for (int at = 0; at < 2; at++)
#pragma unroll
            for (int bp = 0; bp < 2; bp++)
#pragma unroll
                for (int hf = 0; hf < 2; hf++)
                    mma16816(acc[at][bp * 2 + hf], ah[at], &bh[bp][hf * 2]);
#pragma unroll
        for (int at = 0; at < 2; at++)
#pragma unroll
            for (int bp = 0; bp < 2; bp++)
#pragma unroll
                for (int hf = 0; hf < 2; hf++)
                    mma16816(acc[at][bp * 2 + hf], ah[at], &bl[bp][hf * 2]);
#pragma unroll
        for (int at = 0; at < 2; at++)
#pragma unroll
            for (int bp = 0; bp < 2; bp++)
#pragma unroll
                for (int hf = 0; hf < 2; hf++)
                    mma16816(acc[at][bp * 2 + hf], al[at], &bh[bp][hf * 2]);
    }
}

// gemm0 B tile: t (0..31): e=t>>2, sub=t&3, chunk=sub>>1, which=sub&1; buf = t&1
__device__ __forceinline__ void issue_b0(uint32_t smb, uint32_t bufbase,
                                         const char* wth_all, const char* wtl_all,
                                         int t, int tid) {
    int e = t >> 2, sub = t & 3, chunk = sub >> 1, which = sub & 1;
    const char* src = (which ? wtl_all : wth_all)
                    + (size_t)(e * 2) * 65536 + chunk * 32768;
    uint32_t dst = smb + bufbase + (uint32_t)(t & 1) * 32768;
#pragma unroll
    for (int i = 0; i < 2048; i += 512) {
        int idx = tid + i;
        cp16(dst + idx * 16, src + idx * 16);
    }
    CP_COMMIT();
}

// gemm1 B tile: buf fixed by which (0=hi, 1=lo)
__device__ __forceinline__ void issue_b1(uint32_t smb, uint32_t bufbase,
                                         const char* wth, const char* wtl,
                                         int chunk, int which, int tid) {
    const char* src = (which ? wtl : wth) + chunk * 32768;
    uint32_t dst = smb + bufbase + (uint32_t)which * 32768;
#pragma unroll
    for (int i = 0; i < 2048; i += 256) {
        int idx = tid + i;
        cp16(dst + idx * 16, src + idx * 16);
    }
    CP_COMMIT();
}

// ================= batched layer-0 GEMM (512 thr, 1 CTA/SM, pipelined B) ==============
#define G0_B 131072
#define G0_TOTAL 196608

__global__ void __launch_bounds__(512, 1)
k_gemm0_all(const float* __restrict__ x, const float* __restrict__ agg0,
            const char* __restrict__ wth_all, const char* __restrict__ wtl_all,
            const float* __restrict__ bprm, float* __restrict__ h_all)
{
    extern __shared__ char sm[];
    uint32_t smb = smem_u32(sm);
    int tid = threadIdx.x, wid = tid >> 5, lane = tid & 31;
    int n0 = blockIdx.x * 128;
    MmaCtx c;
    c.wr = wid & 3; c.wc = wid >> 2;
    c.lrowA = lane & 15; c.lkgA = lane >> 4;
    c.lnB = (lane & 7) + ((lane >> 4) << 3); c.lkgB = (lane >> 3) & 1;
    int trow = lane >> 2, tc2 = lane & 3;

    convert_A<false, 512, 4096, 32768>(sm, 0,     x,    nullptr, nullptr, n0, tid);
    convert_A<false, 512, 4096, 32768>(sm, 65536, agg0, nullptr, nullptr, n0, tid);

    issue_b0(smb, G0_B, wth_all, wtl_all, 0, tid);

    float acc[2][4][4];
#pragma unroll
    for (int a = 0; a < 2; a++)
#pragma unroll
        for (int b = 0; b < 4; b++)
#pragma unroll
            for (int q = 0; q < 4; q++) acc[a][b][q] = 0.f;

    for (int e = 0; e < NEXP; e++) {
#pragma unroll
        for (int sub = 0; sub < 4; sub++) {
            int t = e * 4 + sub;
            if (t + 1 < 32) {
                issue_b0(smb, G0_B, wth_all, wtl_all, t + 1, tid);
                CP_WAIT1();
            } else {
                CP_WAIT0();
            }
            __syncthreads();
            int ab = (sub >> 1) * 65536;
            int bbase = G0_B + (t & 1) * 32768;
            if ((sub & 1) == 0)
                mma_pass<true>(smb, ab, ab + 32768, bbase, c, acc);
            else
                mma_pass<false>(smb, ab, 0, bbase, c, acc);

            if (sub == 3) {
                const float* be = bprm + (size_t)(e * 2) * DD;
                float2* o = (float2*)(h_all + (size_t)e * NN * DD);
#pragma unroll
                for (int bt = 0; bt < 4; bt++) {
                    int col = c.wc * 32 + bt * 8 + tc2 * 2;
                    float bx = be[col], by = be[col + 1];
                    float sx = 0.f, sy = 0.f, qx = 0.f, qy = 0.f;
#pragma unroll
                    for (int at = 0; at < 2; at++) {
                        int r0 = n0 + c.wr * 32 + at * 16 + trow;
                        float v0x = acc[at][bt][0] + bx, v0y = acc[at][bt][1] + by;
                        float v1x = acc[at][bt][2] + bx, v1y = acc[at][bt][3] + by;
                        if (r0 < NN) {
                            o[r0 * 64 + (col >> 1)] = make_float2(v0x, v0y);
                            sx += v0x; sy += v0y; qx += v0x * v0x; qy += v0y * v0y;
                        }
                        if (r0 + 8 < NN) {
                            o[(r0 + 8) * 64 + (col >> 1)] = make_float2(v1x, v1y);
                            sx += v1x; sy += v1y; qx += v1x * v1x; qy += v1y * v1y;
                        }
                    }
#pragma unroll
                    for (int off = 4; off < 32; off <<= 1) {
                        sx += __shfl_xor_sync(0xFFFFFFFF, sx, off);
                        sy += __shfl_xor_sync(0xFFFFFFFF, sy, off);
                        qx += __shfl_xor_sync(0xFFFFFFFF, qx, off);
                        qy += __shfl_xor_sync(0xFFFFFFFF, qy, off);
                    }
                    if (lane < 4) {
                        atomicAdd(&g_stats_s[e * DD + col], sx);
                        atomicAdd(&g_stats_s[e * DD + col + 1], sy);
                        atomicAdd(&g_stats_q[e * DD + col], qx);
                        atomicAdd(&g_stats_q[e * DD + col + 1], qy);
                    }
                }
#pragma unroll
                for (int a = 0; a < 2; a++)
#pragma unroll
                    for (int b = 0; b < 4; b++)
#pragma unroll
                        for (int q = 0; q < 4; q++) acc[a][b][q] = 0.f;
            }
            __syncthreads();
        }
    }
}

// ================= finalize BN =================
__global__ void k_finalize(const float* __restrict__ gamma, const float* __restrict__ beta) {
    int i = threadIdx.x + blockIdx.x * blockDim.x;
    if (i >= NEXP * DD) return;
    const float invn = 1.0f / (float)NN;
    float m = g_stats_s[i] * invn;
    float var = g_stats_q[i] * invn - m * m;
    float r = rsqrtf(var + EPSV);
    float sc = gamma[i] * r;
    g_scale[i] = sc;
    g_shift[i] = beta[i] - m * sc;
}

// ================= per-expert layer-1 GEMM: M=64 tile, 256 thr, 2 CTAs/SM =============
#define G1_ALO 16384
#define G1_B   32768
#define G1_TOTAL 98304

__global__ void __launch_bounds__(256, 2)
k_gemm1_one(const float* __restrict__ he, const float* __restrict__ ae,
            const char* __restrict__ wth, const char* __restrict__ wtl,
            const float* __restrict__ be,
            const float* __restrict__ scale, const float* __restrict__ shift,
            float* __restrict__ oe)
{
    extern __shared__ char sm[];
    uint32_t smb = smem_u32(sm);
    int tid = threadIdx.x, wid = tid >> 5, lane = tid & 31;
    int n0 = blockIdx.x * 64;
    MmaCtx c;
    c.wr = wid & 1; c.wc = wid >> 1;
    c.lrowA = lane & 15; c.lkgA = lane >> 4;
    c.lnB = (lane & 7) + ((lane >> 4) << 3); c.lkgB = (lane >> 3) & 1;
    int trow = lane >> 2, tc2 = lane & 3;

    issue_b1(smb, G1_B, wth, wtl, 0, 0, tid);
    issue_b1(smb, G1_B, wth, wtl, 0, 1, tid);

    float acc[2][4][4];
#pragma unroll
    for (int a = 0; a < 2; a++)
#pragma unroll
        for (int b = 0; b < 4; b++)
#pragma unroll
            for (int q = 0; q < 4; q++) acc[a][b][q] = 0.f;

#pragma unroll
    for (int chunk = 0; chunk < 2; chunk++) {
        if (chunk == 0)
            convert_A<true, 256, 2048, G1_ALO>(sm, 0, he, scale, shift, n0, tid);
        else
            convert_A<false, 256, 2048, G1_ALO>(sm, 0, ae, nullptr, nullptr, n0, tid);
        CP_WAIT0();
        __syncthreads();
        mma_pass3(smb, 0, G1_ALO, G1_B, G1_B + 32768, c, acc);
        __syncthreads();
        if (chunk == 0) {
            issue_b1(smb, G1_B, wth, wtl, 1, 0, tid);
            issue_b1(smb, G1_B, wth, wtl, 1, 1, tid);
        }
    }

    float2* o = (float2*)oe;
#pragma unroll
    for (int at = 0; at < 2; at++)
#pragma unroll
        for (int bt = 0; bt < 4; bt++) {
            int col = c.wc * 32 + bt * 8 + tc2 * 2;
            float bx = be[col], by = be[col + 1];
            int r0 = n0 + c.wr * 32 + at * 16 + trow;
            if (r0 < NN)
                o[r0 * 64 + (col >> 1)] =
                    make_float2(acc[at][bt][0] + bx, acc[at][bt][1] + by);
            if (r0 + 8 < NN)
                o[(r0 + 8) * 64 + (col >> 1)] =
                    make_float2(acc[at][bt][2] + bx, acc[at][bt][3] + by);
        }
}

// ================= final interleave [8][N][128] -> [N][128][8] =================
__global__ void k_interleave(float* __restrict__ out) {
    int idx = blockIdx.x * blockDim.x + threadIdx.x;
    if (idx >= NN * DD) return;
    float v[8];
#pragma unroll
    for (int e = 0; e < 8; e++) v[e] = g_out_tmp[(size_t)e * (NN * DD) + idx];
    float4* o = (float4*)out + (size_t)idx * 2;
    o[0] = make_float4(v[0], v[1], v[2], v[3]);
    o[1] = make_float4(v[4], v[5], v[6], v[7]);
}

// ================= launch =================
extern "C" void kernel_launch(void* const* d_in, const int* in_sizes, int n_in,
                              void* d_out, int out_size)
{
    const float* x      = (const float*)d_in[0];
    const int*   ei32   = (const int*)d_in[1];
    const float* W_self = (const float*)d_in[2];
    const float* W_nbr  = (const float*)d_in[3];
    const float* bprm   = (const float*)d_in[4];
    const float* gamma  = (const float*)d_in[5];
    const float* beta   = (const float*)d_in[6];
    float*       out    = (float*)d_out;

    cudaFuncSetAttribute(k_gemm0_all, cudaFuncAttributeMaxDynamicSharedMemorySize, G0_TOTAL);
    cudaFuncSetAttribute(k_gemm1_one, cudaFuncAttributeMaxDynamicSharedMemorySize, G1_TOTAL);

    float *agg0, *agg1, *hall, *otmp, *scl, *shf;
    char *wth, *wtl;
    cudaGetSymbolAddress((void**)&agg0, g_agg0);
    cudaGetSymbolAddress((void**)&agg1, g_agg1_all);
    cudaGetSymbolAddress((void**)&hall, g_h_all);
    cudaGetSymbolAddress((void**)&otmp, g_out_tmp);
    cudaGetSymbolAddress((void**)&scl,  g_scale);
    cudaGetSymbolAddress((void**)&shf,  g_shift);
    cudaGetSymbolAddress((void**)&wth,  g_wt_hi);
    cudaGetSymbolAddress((void**)&wtl,  g_wt_lo);

    const int NB0 = (NN + 127) / 128;   // 782
    const int NB1 = (NN + 63) / 64;     // 1563
    cudaStream_t s0 = 0;
    cudaStream_t s2 = g_ss.s2;

    // fork: side stream joins the capture via event
    k_init<<<1, 1024, 0, s0>>>(ei32);
    cudaEventRecord(g_ss.evFork, s0);
    cudaStreamWaitEvent(s2, g_ss.evFork, 0);

    // prep_w (s2) overlaps csr_agg0 (s0)
    k_prep_w<<<16, 256, 0, s2>>>(W_self, W_nbr);
    cudaEventRecord(g_ss.evPrep, s2);
    k_csr_agg0<<<NBLK, 256, 0, s0>>>(ei32, x, agg0);

    // gemm0 needs both
    cudaStreamWaitEvent(s0, g_ss.evPrep, 0);
    k_gemm0_all<<<NB0, 512, G0_TOTAL, s0>>>(x, agg0, wth, wtl, bprm, hall);
    k_finalize<<<1, 1024, 0, s0>>>(gamma, beta);

    // pipelined per-expert: agg(e) on s0, gemm1(e) on s2 (high priority)
    for (int e = 0; e < NEXP; e++) {
        const float* he = hall + (size_t)e * NN * DD;
        float*       ae = agg1 + (size_t)e * NN * DD;
        k_agg<<<NN / 8, 256, 0, s0>>>(he, ae, scl + e * DD, shf + e * DD);
        cudaEventRecord(g_ss.evA[e], s0);
        cudaStreamWaitEvent(s2, g_ss.evA[e], 0);
        k_gemm1_one<<<NB1, 256, G1_TOTAL, s2>>>(
            he, ae,
            (const char*)(wth + (size_t)(e * 2 + 1) * 65536),
            (const char*)(wtl + (size_t)(e * 2 + 1) * 65536),
            bprm + (size_t)(e * 2 + 1) * DD,
            scl + e * DD, shf + e * DD,
            otmp + (size_t)e * NN * DD);
    }

    // join: interleave after last gemm1
    cudaEventRecord(g_ss.evG, s2);
    cudaStreamWaitEvent(s0, g_ss.evG, 0);
    k_interleave<<<(NN * DD) / 256, 256, 0, s0>>>(out);
}